// round 6
// baseline (speedup 1.0000x reference)
#include <cuda_runtime.h>
#include <cuda_bf16.h>

// Scratch for per-batch means of q,k,v: [batch][9] = (mq.xyz, mk.xyz, mv.xyz)
__device__ float g_means[16 * 9];

#define MAX_N 2048

// ---------------------------------------------------------------------------
// Kernel 1: per-batch means of q, k, v. One block per batch.
// ---------------------------------------------------------------------------
__global__ void vsa_means_kernel(const float* __restrict__ q,
                                 const float* __restrict__ k,
                                 const float* __restrict__ v,
                                 int N) {
    const int b = blockIdx.x;
    const float* qb = q + (size_t)b * N * 3;
    const float* kb = k + (size_t)b * N * 3;
    const float* vb = v + (size_t)b * N * 3;

    float s[9];
#pragma unroll
    for (int c = 0; c < 9; c++) s[c] = 0.0f;

    for (int i = threadIdx.x; i < N; i += blockDim.x) {
        const int o = i * 3;
        s[0] += qb[o + 0]; s[1] += qb[o + 1]; s[2] += qb[o + 2];
        s[3] += kb[o + 0]; s[4] += kb[o + 1]; s[5] += kb[o + 2];
        s[6] += vb[o + 0]; s[7] += vb[o + 1]; s[8] += vb[o + 2];
    }

#pragma unroll
    for (int c = 0; c < 9; c++) {
#pragma unroll
        for (int off = 16; off > 0; off >>= 1)
            s[c] += __shfl_xor_sync(0xFFFFFFFFu, s[c], off);
    }

    __shared__ float red[8][9];
    const int warp = threadIdx.x >> 5;
    const int lane = threadIdx.x & 31;
    if (lane == 0) {
#pragma unroll
        for (int c = 0; c < 9; c++) red[warp][c] = s[c];
    }
    __syncthreads();

    const int nwarps = blockDim.x >> 5;
    if (threadIdx.x < 9) {
        float t = 0.0f;
        for (int w = 0; w < nwarps; w++) t += red[w][threadIdx.x];
        g_means[b * 9 + threadIdx.x] = t / (float)N;
    }
}

// ---------------------------------------------------------------------------
// Packed f32x2 helpers (Blackwell FFMA2 path — only reachable via PTX).
// ---------------------------------------------------------------------------
#define F32X2_MUL(d, a, b) \
    asm("mul.rn.f32x2 %0, %1, %2;" : "=l"(d) : "l"(a), "l"(b))
#define F32X2_ADD(d, a, b) \
    asm("add.rn.f32x2 %0, %1, %2;" : "=l"(d) : "l"(a), "l"(b))
#define F32X2_FMA(d, a, b, c) \
    asm("fma.rn.f32x2 %0, %1, %2, %3;" : "=l"(d) : "l"(a), "l"(b), "l"(c))
#define F32X2_PACK(d, lo, hi) \
    asm("mov.b64 %0, {%1, %2};" : "=l"(d) : "f"(lo), "f"(hi))
#define F32X2_UNPACK(lo, hi, s) \
    asm("mov.b64 {%0, %1}, %2;" : "=f"(lo), "=f"(hi) : "l"(s))

// ---------------------------------------------------------------------------
// Kernel 2: main. grid = (N/8, B), 256 threads (8 warps). Warp owns row i;
// each lane takes 4 consecutive j's per step (j = 4*lane + 128*step).
//
// k is staged centered AND pre-scaled by c1 = log2e/sqrt(N), in a
// pair-interleaved layout per 4-j group:
//     [x0,x1,y0,y1 | z0,z1,x2,x3 | y2,y3,z2,z3]   (48 B, 16B-aligned)
// so three ld.shared.v2.f64 yield six ready-made f32x2 operands with ZERO
// packing movs. 48-byte lane stride -> all 32 banks hit exactly once per
// 8-lane phase: conflict-free.
//
// Math per 2 j's is done in packed f32x2 (FFMA2): 15 fma/alu-pipe insts +
// 4 scalar MUFU (sqrt, ex2), ~halving the per-pair issue count.
//   e = ex2(sqrt(|q_c x k_c'|^2)),  T' = sum e*C',  fixed up by /c1 at the end.
// ---------------------------------------------------------------------------
__global__ __launch_bounds__(256, 7)
void vsa_main_kernel(const float* __restrict__ q,
                     const float* __restrict__ k,
                     const float* __restrict__ v,
                     float* __restrict__ out,
                     int N) {
    __shared__ double2 skd[MAX_N * 3 / 4];  // 1536 * 16B = 24 KB

    const int b = blockIdx.y;
    const float* mp = &g_means[b * 9];
    const float mqx = mp[0], mqy = mp[1], mqz = mp[2];
    const float mkx = mp[3], mky = mp[4], mkz = mp[5];
    const float mvx = mp[6], mvy = mp[7], mvz = mp[8];

    const float c1 = 1.4426950408889634f * rsqrtf((float)N);  // log2e/sqrt(N)

    // Stage centered + pre-scaled k into the pair-interleaved layout.
    {
        float* sk = (float*)skd;
        const float* kb = k + (size_t)b * N * 3;
        for (int idx = threadIdx.x; idx < N * 3; idx += blockDim.x) {
            const int j = idx / 3;
            const int c = idx - 3 * j;
            const int g  = j >> 2;        // 4-j group
            const int jj = j & 3;
            const int pr = jj >> 1;       // pair within group
            const int w  = jj & 1;        // slot within pair
            const float m = (c == 0) ? mkx : ((c == 1) ? mky : mkz);
            sk[g * 12 + pr * 6 + c * 2 + w] = (kb[idx] - m) * c1;
        }
    }
    __syncthreads();

    const int warp = threadIdx.x >> 5;
    const int lane = threadIdx.x & 31;
    const int i = blockIdx.x * 8 + warp;

    const float* qi = q + ((size_t)b * N + i) * 3;
    const float qx = qi[0] - mqx;
    const float qy = qi[1] - mqy;
    const float qz = qi[2] - mqz;

    // Packed (broadcast) q and -q constants.
    unsigned long long qx2, qy2, qz2, nqx2, nqy2, nqz2;
    F32X2_PACK(qx2, qx, qx);   F32X2_PACK(qy2, qy, qy);   F32X2_PACK(qz2, qz, qz);
    F32X2_PACK(nqx2, -qx, -qx); F32X2_PACK(nqy2, -qy, -qy); F32X2_PACK(nqz2, -qz, -qz);

    unsigned long long sumE2 = 0ull, Tx2 = 0ull, Ty2 = 0ull, Tz2 = 0ull;

    const double2* p = skd + 3 * lane;
    const int nsteps = N >> 7;  // N / 128

    // Two pairs (2 j's) in packed f32x2 per invocation.
#define VSA_PAIR2(KX, KY, KZ)                                               \
    {                                                                       \
        unsigned long long t_, Cx2_, Cy2_, Cz2_, m_, e2_;                   \
        F32X2_MUL(t_, nqz2, (KY));  F32X2_FMA(Cx2_, qy2, (KZ), t_);         \
        F32X2_MUL(t_, nqx2, (KZ));  F32X2_FMA(Cy2_, qz2, (KX), t_);         \
        F32X2_MUL(t_, nqy2, (KX));  F32X2_FMA(Cz2_, qx2, (KY), t_);         \
        F32X2_MUL(m_, Cz2_, Cz2_);                                          \
        F32X2_FMA(m_, Cy2_, Cy2_, m_);                                      \
        F32X2_FMA(m_, Cx2_, Cx2_, m_);                                      \
        float na_, nb_, ea_, eb_;                                           \
        F32X2_UNPACK(na_, nb_, m_);                                         \
        asm("sqrt.approx.f32 %0, %1;" : "=f"(ea_) : "f"(na_));              \
        asm("ex2.approx.f32 %0, %1;"  : "=f"(ea_) : "f"(ea_));              \
        asm("sqrt.approx.f32 %0, %1;" : "=f"(eb_) : "f"(nb_));              \
        asm("ex2.approx.f32 %0, %1;"  : "=f"(eb_) : "f"(eb_));              \
        F32X2_PACK(e2_, ea_, eb_);                                          \
        F32X2_ADD(sumE2, sumE2, e2_);                                       \
        F32X2_FMA(Tx2, e2_, Cx2_, Tx2);                                     \
        F32X2_FMA(Ty2, e2_, Cy2_, Ty2);                                     \
        F32X2_FMA(Tz2, e2_, Cz2_, Tz2);                                     \
    }

#pragma unroll 2
    for (int s = 0; s < nsteps; s++) {
        const double2 d0 = p[0];   // (x0,x1) (y0,y1)
        const double2 d1 = p[1];   // (z0,z1) (x2,x3)
        const double2 d2 = p[2];   // (y2,y3) (z2,z3)
        p += 96;  // 128 j's * 12 B / 16 B
        const unsigned long long kxA = (unsigned long long)__double_as_longlong(d0.x);
        const unsigned long long kyA = (unsigned long long)__double_as_longlong(d0.y);
        const unsigned long long kzA = (unsigned long long)__double_as_longlong(d1.x);
        const unsigned long long kxB = (unsigned long long)__double_as_longlong(d1.y);
        const unsigned long long kyB = (unsigned long long)__double_as_longlong(d2.x);
        const unsigned long long kzB = (unsigned long long)__double_as_longlong(d2.y);
        VSA_PAIR2(kxA, kyA, kzA)
        VSA_PAIR2(kxB, kyB, kzB)
    }
#undef VSA_PAIR2

    // Horizontal: collapse packed halves, then warp reduce.
    float sumE, Tx, Ty, Tz;
    {
        float a0, a1;
        F32X2_UNPACK(a0, a1, sumE2); sumE = a0 + a1;
        F32X2_UNPACK(a0, a1, Tx2);   Tx = a0 + a1;
        F32X2_UNPACK(a0, a1, Ty2);   Ty = a0 + a1;
        F32X2_UNPACK(a0, a1, Tz2);   Tz = a0 + a1;
    }

#pragma unroll
    for (int off = 16; off > 0; off >>= 1) {
        sumE += __shfl_xor_sync(0xFFFFFFFFu, sumE, off);
        Tx   += __shfl_xor_sync(0xFFFFFFFFu, Tx,   off);
        Ty   += __shfl_xor_sync(0xFFFFFFFFu, Ty,   off);
        Tz   += __shfl_xor_sync(0xFFFFFFFFu, Tz,   off);
    }

    if (lane == 0) {
        const float* vi = v + ((size_t)b * N + i) * 3;
        const float vx = vi[0] - mvx;
        const float vy = vi[1] - mvy;
        const float vz = vi[2] - mvz;
        // T' = c1 * T  ->  divide by c1 here as well as by Z*N
        const float inv = 1.0f / (sumE * (float)N * c1);
        float* o = out + ((size_t)b * N + i) * 3;
        o[0] = fmaf(Ty, vz, -Tz * vy) * inv;
        o[1] = fmaf(Tz, vx, -Tx * vz) * inv;
        o[2] = fmaf(Tx, vy, -Ty * vx) * inv;
    }
}

// ---------------------------------------------------------------------------
extern "C" void kernel_launch(void* const* d_in, const int* in_sizes, int n_in,
                              void* d_out, int out_size) {
    const float* q = (const float*)d_in[0];
    const float* k = (const float*)d_in[1];
    const float* v = (const float*)d_in[2];
    float* out = (float*)d_out;

    const int N = 2048;                 // fixed by problem spec
    const int B = out_size / (N * 3);   // = 4

    vsa_means_kernel<<<B, 256>>>(q, k, v, N);

    dim3 grid(N / 8, B);
    vsa_main_kernel<<<grid, 256>>>(q, k, v, out, N);
}

// round 7
// speedup vs baseline: 1.0960x; 1.0960x over previous
#include <cuda_runtime.h>
#include <cuda_bf16.h>

// Scratch for per-batch means of q,k,v: [batch][9] = (mq.xyz, mk.xyz, mv.xyz)
__device__ float g_means[16 * 9];

#define MAX_N 2048

// ---------------------------------------------------------------------------
// Kernel 1: per-batch means of q, k, v. One block per batch.
// ---------------------------------------------------------------------------
__global__ void vsa_means_kernel(const float* __restrict__ q,
                                 const float* __restrict__ k,
                                 const float* __restrict__ v,
                                 int N) {
    const int b = blockIdx.x;
    const float* qb = q + (size_t)b * N * 3;
    const float* kb = k + (size_t)b * N * 3;
    const float* vb = v + (size_t)b * N * 3;

    float s[9];
#pragma unroll
    for (int c = 0; c < 9; c++) s[c] = 0.0f;

    for (int i = threadIdx.x; i < N; i += blockDim.x) {
        const int o = i * 3;
        s[0] += qb[o + 0]; s[1] += qb[o + 1]; s[2] += qb[o + 2];
        s[3] += kb[o + 0]; s[4] += kb[o + 1]; s[5] += kb[o + 2];
        s[6] += vb[o + 0]; s[7] += vb[o + 1]; s[8] += vb[o + 2];
    }

#pragma unroll
    for (int c = 0; c < 9; c++) {
#pragma unroll
        for (int off = 16; off > 0; off >>= 1)
            s[c] += __shfl_xor_sync(0xFFFFFFFFu, s[c], off);
    }

    __shared__ float red[8][9];
    const int warp = threadIdx.x >> 5;
    const int lane = threadIdx.x & 31;
    if (lane == 0) {
#pragma unroll
        for (int c = 0; c < 9; c++) red[warp][c] = s[c];
    }
    __syncthreads();

    const int nwarps = blockDim.x >> 5;
    if (threadIdx.x < 9) {
        float t = 0.0f;
        for (int w = 0; w < nwarps; w++) t += red[w][threadIdx.x];
        g_means[b * 9 + threadIdx.x] = t / (float)N;
    }
}

// ---------------------------------------------------------------------------
// Kernel 2: main. grid = (N/16, B), 512 threads (16 warps, 16 rows/block).
//
// ALGEBRA: T_i = sum_j e_ij (q_i x k_j) = q_i x (sum_j e_ij k_j).
// So the hot loop only needs e_ij = exp(|q_i x k_j| / sqrt(N)) and the
// accumulators Z = sum e, W = sum e*k'.  The norm comes from Lagrange:
//   |q x k|^2 = |q|^2 |k|^2 - (q.k)^2
// k is staged as float4 (k'.xyz, |k'|^2) with k' = (k - mk) * c1,
// c1 = log2e/sqrt(N)  =>  e = ex2(sqrt(|q x k'|^2))  (raw MUFUs, no wrapper).
// Per pair: 3 FMA dot + 1 MUL + 1 FMA (n2) + FMNMX clamp + sqrt + ex2 +
// 4 accum FMA + 1 LDS.128  (~12 issue slots vs ~17.5 before).
//
// Occupancy: 32 KB tile + 1 KB reserved per block. 512-thr blocks =>
// 4 blocks/SM (132 KB, 64 warps = full), grid 512 <= capacity 592: ONE wave.
// __launch_bounds__(512,4) caps regs at 32.
// ---------------------------------------------------------------------------
__global__ __launch_bounds__(512, 4)
void vsa_main_kernel(const float* __restrict__ q,
                     const float* __restrict__ k,
                     const float* __restrict__ v,
                     float* __restrict__ out,
                     int N) {
    __shared__ float4 sk[MAX_N];  // 32 KB

    const int b = blockIdx.y;
    const float* mp = &g_means[b * 9];
    const float mqx = mp[0], mqy = mp[1], mqz = mp[2];
    const float mkx = mp[3], mky = mp[4], mkz = mp[5];
    const float mvx = mp[6], mvy = mp[7], mvz = mp[8];

    const float c1 = 1.4426950408889634f * rsqrtf((float)N);  // log2e/sqrt(N)

    // Stage k': one thread per j computes (k-mk)*c1 and |k'|^2.
    {
        const float* kb = k + (size_t)b * N * 3;
        for (int j = threadIdx.x; j < N; j += blockDim.x) {
            const float kx = (kb[j * 3 + 0] - mkx) * c1;
            const float ky = (kb[j * 3 + 1] - mky) * c1;
            const float kz = (kb[j * 3 + 2] - mkz) * c1;
            const float kk = fmaf(kx, kx, fmaf(ky, ky, kz * kz));
            sk[j] = make_float4(kx, ky, kz, kk);
        }
    }
    __syncthreads();

    const int warp = threadIdx.x >> 5;
    const int lane = threadIdx.x & 31;
    const int i = blockIdx.x * 16 + warp;

    const float* qi = q + ((size_t)b * N + i) * 3;
    const float qx = qi[0] - mqx;
    const float qy = qi[1] - mqy;
    const float qz = qi[2] - mqz;
    const float qq = fmaf(qx, qx, fmaf(qy, qy, qz * qz));  // |q_c|^2

    float Z = 0.0f, Wx = 0.0f, Wy = 0.0f, Wz = 0.0f;

#define VSA_PAIR(F)                                                  \
    {                                                                \
        const float dot = fmaf(qx, (F).x, fmaf(qy, (F).y, qz * (F).z)); \
        float n2 = fmaf(-dot, dot, qq * (F).w);                      \
        n2 = fmaxf(n2, 0.0f);  /* cancellation can go slightly <0 */ \
        float e;                                                     \
        asm("sqrt.approx.f32 %0, %1;" : "=f"(e) : "f"(n2));          \
        asm("ex2.approx.f32 %0, %1;"  : "=f"(e) : "f"(e));           \
        Z += e;                                                      \
        Wx = fmaf(e, (F).x, Wx);                                     \
        Wy = fmaf(e, (F).y, Wy);                                     \
        Wz = fmaf(e, (F).z, Wz);                                     \
    }

    // lanes stride j; unroll 2 (reg budget: 32 under launch_bounds(512,4))
#pragma unroll 2
    for (int j = lane; j < N; j += 32) {
        const float4 f = sk[j];
        VSA_PAIR(f)
    }
#undef VSA_PAIR

    // warp reduction of Z, W
#pragma unroll
    for (int off = 16; off > 0; off >>= 1) {
        Z  += __shfl_xor_sync(0xFFFFFFFFu, Z,  off);
        Wx += __shfl_xor_sync(0xFFFFFFFFu, Wx, off);
        Wy += __shfl_xor_sync(0xFFFFFFFFu, Wy, off);
        Wz += __shfl_xor_sync(0xFFFFFFFFu, Wz, off);
    }

    if (lane == 0) {
        // T' = q x W  (= c1 * T). u = cross(T'/(Z*N*c1), v_c)... expanded:
        const float Tx = fmaf(qy, Wz, -qz * Wy);
        const float Ty = fmaf(qz, Wx, -qx * Wz);
        const float Tz = fmaf(qx, Wy, -qy * Wx);
        const float* vi = v + ((size_t)b * N + i) * 3;
        const float vx = vi[0] - mvx;
        const float vy = vi[1] - mvy;
        const float vz = vi[2] - mvz;
        const float inv = 1.0f / (Z * (float)N * c1);
        float* o = out + ((size_t)b * N + i) * 3;
        o[0] = fmaf(Ty, vz, -Tz * vy) * inv;
        o[1] = fmaf(Tz, vx, -Tx * vz) * inv;
        o[2] = fmaf(Tx, vy, -Ty * vx) * inv;
    }
}

// ---------------------------------------------------------------------------
extern "C" void kernel_launch(void* const* d_in, const int* in_sizes, int n_in,
                              void* d_out, int out_size) {
    const float* q = (const float*)d_in[0];
    const float* k = (const float*)d_in[1];
    const float* v = (const float*)d_in[2];
    float* out = (float*)d_out;

    const int N = 2048;                 // fixed by problem spec
    const int B = out_size / (N * 3);   // = 4

    vsa_means_kernel<<<B, 256>>>(q, k, v, N);

    dim3 grid(N / 16, B);
    vsa_main_kernel<<<grid, 512>>>(q, k, v, out, N);
}

// round 8
// speedup vs baseline: 1.3918x; 1.2698x over previous
#include <cuda_runtime.h>
#include <cuda_bf16.h>

#define VSA_N   2048
#define VSA_BLK 512
#define VSA_ROWS_PER_BLK 16  // warps per block, one output row per warp

// ---------------------------------------------------------------------------
// Single fused kernel. grid = (N/16, B), 512 threads (16 warps).
//
// Phase A: block-redundant means of q,k,v for its batch (all L2-resident:
//          128 blocks share each batch's 75 KB slice).
// Phase B: stage k' = (k - mk) * c1 as float4 (xyz, |k'|^2), c1 = log2e/sqrt(N).
// Phase C: hot loop. ALGEBRA: T_i = q_i x (sum_j e_ij k_j), and
//          |q x k|^2 = |q|^2|k|^2 - (q.k)^2 (Lagrange), so per pair only:
//          3 FMA dot + MUL/FMA n2 + FMNMX clamp + MUFU sqrt + MUFU ex2 +
//          4 accum + 1 LDS.128.  e = ex2(sqrt(n2')) with no exp wrapper.
//          N compile-time => static trip count 64, unroll 8, batched loads.
// Phase D: warp reduce (Z, W), epilogue cross products on lane 0.
// ---------------------------------------------------------------------------
__global__ __launch_bounds__(VSA_BLK, 4)
void vsa_fused_kernel(const float* __restrict__ q,
                      const float* __restrict__ k,
                      const float* __restrict__ v,
                      float* __restrict__ out) {
    __shared__ float4 sk[VSA_N];        // 32 KB
    __shared__ float  red[VSA_BLK / 32][9];
    __shared__ float  means[9];

    const int tid  = threadIdx.x;
    const int b    = blockIdx.y;
    const int warp = tid >> 5;
    const int lane = tid & 31;

    const float* qb = q + (size_t)b * VSA_N * 3;
    const float* kb = k + (size_t)b * VSA_N * 3;
    const float* vb = v + (size_t)b * VSA_N * 3;

    // ---- Phase A: per-batch means (block-redundant) ----
    {
        float s[9];
#pragma unroll
        for (int c = 0; c < 9; c++) s[c] = 0.0f;

#pragma unroll
        for (int r = 0; r < VSA_N / VSA_BLK; r++) {
            const int o = (tid + r * VSA_BLK) * 3;
            s[0] += qb[o + 0]; s[1] += qb[o + 1]; s[2] += qb[o + 2];
            s[3] += kb[o + 0]; s[4] += kb[o + 1]; s[5] += kb[o + 2];
            s[6] += vb[o + 0]; s[7] += vb[o + 1]; s[8] += vb[o + 2];
        }
#pragma unroll
        for (int c = 0; c < 9; c++) {
#pragma unroll
            for (int off = 16; off > 0; off >>= 1)
                s[c] += __shfl_xor_sync(0xFFFFFFFFu, s[c], off);
        }
        if (lane == 0) {
#pragma unroll
            for (int c = 0; c < 9; c++) red[warp][c] = s[c];
        }
        __syncthreads();
        if (tid < 9) {
            float t = 0.0f;
#pragma unroll
            for (int w = 0; w < VSA_BLK / 32; w++) t += red[w][tid];
            means[tid] = t * (1.0f / (float)VSA_N);
        }
        __syncthreads();
    }

    const float mqx = means[0], mqy = means[1], mqz = means[2];
    const float mkx = means[3], mky = means[4], mkz = means[5];
    const float mvx = means[6], mvy = means[7], mvz = means[8];

    // c1 = log2(e) / sqrt(N)
    const float c1 = 1.4426950408889634f * 0.022097086912079612f;  // *1/sqrt(2048)

    // ---- Phase B: stage k' (re-read k; L2-hot from phase A) ----
#pragma unroll
    for (int r = 0; r < VSA_N / VSA_BLK; r++) {
        const int j = tid + r * VSA_BLK;
        const float kx = (kb[j * 3 + 0] - mkx) * c1;
        const float ky = (kb[j * 3 + 1] - mky) * c1;
        const float kz = (kb[j * 3 + 2] - mkz) * c1;
        const float kk = fmaf(kx, kx, fmaf(ky, ky, kz * kz));
        sk[j] = make_float4(kx, ky, kz, kk);
    }
    __syncthreads();

    // ---- Phase C: hot loop ----
    const int i = blockIdx.x * VSA_ROWS_PER_BLK + warp;

    const float* qi = qb + i * 3;
    const float qx = qi[0] - mqx;
    const float qy = qi[1] - mqy;
    const float qz = qi[2] - mqz;
    const float qq = fmaf(qx, qx, fmaf(qy, qy, qz * qz));

    float Z = 0.0f, Wx = 0.0f, Wy = 0.0f, Wz = 0.0f;

#pragma unroll 8
    for (int s = 0; s < VSA_N / 32; s++) {
        const float4 f = sk[s * 32 + lane];
        const float dot = fmaf(qx, f.x, fmaf(qy, f.y, qz * f.z));
        float n2 = fmaf(-dot, dot, qq * f.w);
        n2 = fmaxf(n2, 0.0f);   // cancellation can go slightly < 0
        float e;
        asm("sqrt.approx.f32 %0, %1;" : "=f"(e) : "f"(n2));
        asm("ex2.approx.f32 %0, %1;"  : "=f"(e) : "f"(e));
        Z += e;
        Wx = fmaf(e, f.x, Wx);
        Wy = fmaf(e, f.y, Wy);
        Wz = fmaf(e, f.z, Wz);
    }

    // ---- Phase D: reduce + epilogue ----
#pragma unroll
    for (int off = 16; off > 0; off >>= 1) {
        Z  += __shfl_xor_sync(0xFFFFFFFFu, Z,  off);
        Wx += __shfl_xor_sync(0xFFFFFFFFu, Wx, off);
        Wy += __shfl_xor_sync(0xFFFFFFFFu, Wy, off);
        Wz += __shfl_xor_sync(0xFFFFFFFFu, Wz, off);
    }

    if (lane == 0) {
        // T' = q x W (= c1 * T);  u = cross(T, v_c) / (Z * N)
        const float Tx = fmaf(qy, Wz, -qz * Wy);
        const float Ty = fmaf(qz, Wx, -qx * Wz);
        const float Tz = fmaf(qx, Wy, -qy * Wx);
        const float vx = vb[i * 3 + 0] - mvx;
        const float vy = vb[i * 3 + 1] - mvy;
        const float vz = vb[i * 3 + 2] - mvz;
        const float inv = 1.0f / (Z * (float)VSA_N * c1);
        float* o = out + ((size_t)b * VSA_N + i) * 3;
        o[0] = fmaf(Ty, vz, -Tz * vy) * inv;
        o[1] = fmaf(Tz, vx, -Tx * vz) * inv;
        o[2] = fmaf(Tx, vy, -Ty * vx) * inv;
    }
}

// ---------------------------------------------------------------------------
extern "C" void kernel_launch(void* const* d_in, const int* in_sizes, int n_in,
                              void* d_out, int out_size) {
    const float* q = (const float*)d_in[0];
    const float* k = (const float*)d_in[1];
    const float* v = (const float*)d_in[2];
    float* out = (float*)d_out;

    const int B = out_size / (VSA_N * 3);   // = 4

    dim3 grid(VSA_N / VSA_ROWS_PER_BLK, B); // (128, 4)
    vsa_fused_kernel<<<grid, VSA_BLK>>>(q, k, v, out);
}